// round 15
// baseline (speedup 1.0000x reference)
#include <cuda_runtime.h>
#include <cuda_bf16.h>
#include <math.h>

#define BQ 16
#define TT 64
#define HH 1024
#define NNDIM 4096
#define G3 3072

typedef unsigned long long u64;
typedef unsigned int u32;

// ---------- device scratch ----------
__device__ float g_gates[BQ * TT * G3];
__device__ float g_hbuf[BQ * HH];                        // final h for decoder
// h image, mma-A-fragment layout: [c16 chunk 0..63][lane 0..31][reg 0..3][half]
// hi at [0,32KB), lo at [32KB,64KB). Two ping-pong buffers.
__device__ __align__(16) unsigned char g_img[2][65536];
__device__ unsigned g_count = 0;
__device__ volatile unsigned g_gen = 0;
__device__ unsigned short g_wcvt[(size_t)G3 * 3 * NNDIM];
__device__ unsigned short g_acvt[(size_t)BQ * TT * 3 * NNDIM];

__device__ __forceinline__ u32 smem_u32(const void* p) {
    u32 a; asm("{ .reg .u64 t; cvta.to.shared.u64 t, %1; cvt.u32.u64 %0, t; }" : "=r"(a) : "l"(p));
    return a;
}
__device__ __forceinline__ void cp_async16(u32 dst, const void* src) {
    asm volatile("cp.async.cg.shared.global [%0], [%1], 16;" :: "r"(dst), "l"(src) : "memory");
}
__device__ __forceinline__ void cp_commit() {
    asm volatile("cp.async.commit_group;" ::: "memory");
}
__device__ __forceinline__ void cp_wait1() {
    asm volatile("cp.async.wait_group 1;" ::: "memory");
}
__device__ __forceinline__ void ldsm_x4(u32* r, u32 addr) {
    asm volatile("ldmatrix.sync.aligned.m8n8.x4.shared.b16 {%0,%1,%2,%3}, [%4];"
                 : "=r"(r[0]), "=r"(r[1]), "=r"(r[2]), "=r"(r[3]) : "r"(addr));
}
__device__ __forceinline__ void ld4cg(u32* r, const void* p) {
    asm volatile("ld.global.cg.v4.u32 {%0,%1,%2,%3}, [%4];"
                 : "=r"(r[0]), "=r"(r[1]), "=r"(r[2]), "=r"(r[3]) : "l"(p));
}
__device__ __forceinline__ void mma16816(float* c, const u32* a, const u32* b) {
    asm volatile(
        "mma.sync.aligned.m16n8k16.row.col.f32.bf16.bf16.f32 "
        "{%0,%1,%2,%3}, {%4,%5,%6,%7}, {%8,%9}, {%0,%1,%2,%3};"
        : "+f"(c[0]), "+f"(c[1]), "+f"(c[2]), "+f"(c[3])
        : "r"(a[0]), "r"(a[1]), "r"(a[2]), "r"(a[3]), "r"(b[0]), "r"(b[1]));
}

// hi/lo split of 8 floats -> two packed uint4 of bf16
__device__ __forceinline__ void cvt8_split(float4 f0, float4 f1, uint4& hiw, uint4& low) {
    float v[8] = { f0.x, f0.y, f0.z, f0.w, f1.x, f1.y, f1.z, f1.w };
    unsigned short h[8], l[8];
#pragma unroll
    for (int k = 0; k < 8; ++k) {
        __nv_bfloat16 hb = __float2bfloat16(v[k]);
        __nv_bfloat16 lb = __float2bfloat16(v[k] - __bfloat162float(hb));
        h[k] = *(unsigned short*)&hb;
        l[k] = *(unsigned short*)&lb;
    }
    hiw.x = (u32)h[0] | ((u32)h[1] << 16); hiw.y = (u32)h[2] | ((u32)h[3] << 16);
    hiw.z = (u32)h[4] | ((u32)h[5] << 16); hiw.w = (u32)h[6] | ((u32)h[7] << 16);
    low.x = (u32)l[0] | ((u32)l[1] << 16); low.y = (u32)l[2] | ((u32)l[3] << 16);
    low.z = (u32)l[4] | ((u32)l[5] << 16); low.w = (u32)l[6] | ((u32)l[7] << 16);
}

// =====================================================================
// conv_split_rm: fp32 [rows, K] -> split-bf16 row-major [rows, 3K]
// rz=1: first 16 blocks additionally zero g_img[0].
// =====================================================================
__global__ void conv_split_rm(const float* __restrict__ src, unsigned short* __restrict__ dst,
                              int K, int total, int a_mode, int rz)
{
    if (rz && blockIdx.x < 16) {
        int i = blockIdx.x * 256 + threadIdx.x;
        if (i < 4096) ((uint4*)g_img[0])[i] = make_uint4(0u, 0u, 0u, 0u);
    }
    int t = blockIdx.x * blockDim.x + threadIdx.x;
    if (t >= total) return;
    int kg = t % (K >> 3);
    int r  = t / (K >> 3);
    const float4* p = (const float4*)(src + (size_t)r * K + kg * 8);
    float v[8];
    float4 f0 = __ldg(p), f1 = __ldg(p + 1);
    v[0]=f0.x; v[1]=f0.y; v[2]=f0.z; v[3]=f0.w;
    v[4]=f1.x; v[5]=f1.y; v[6]=f1.z; v[7]=f1.w;
    unsigned short o[24];
#pragma unroll
    for (int k = 0; k < 8; ++k) {
        __nv_bfloat16 hi = __float2bfloat16(v[k]);
        __nv_bfloat16 lo = __float2bfloat16(v[k] - __bfloat162float(hi));
        unsigned short hs = *(unsigned short*)&hi;
        unsigned short ls = *(unsigned short*)&lo;
        o[3*k+0] = hs;
        o[3*k+1] = a_mode ? ls : hs;
        o[3*k+2] = a_mode ? hs : ls;
    }
    unsigned short* d = dst + (size_t)r * 3 * K + (size_t)kg * 24;
    ((uint4*)d)[0] = ((uint4*)o)[0];
    ((uint4*)d)[1] = ((uint4*)o)[1];
    ((uint4*)d)[2] = ((uint4*)o)[2];
}

// =====================================================================
// bf16 tensor-core GEMM: CTA 128x192, one wave (16x8 grid).
// R15 change: trailing __syncthreads removed (redundant — loads for
// stage i+2 are issued after the top sync of iter i, which already
// guarantees all warps finished compute of iter i-1, the only reader
// of that buffer).
// =====================================================================
#define GEMM_BN 192
#define GEMM_STAGE 20480
#define GEMM_SMEM (3 * GEMM_STAGE)

__global__ void __launch_bounds__(256, 1) gemm_bf16_tc(
    const unsigned short* __restrict__ A, const unsigned short* __restrict__ W,
    const float* __restrict__ bias, float* __restrict__ C, int Keff)
{
    extern __shared__ __align__(1024) char buf[];

    const int tid  = threadIdx.x;
    const int wid  = tid >> 5;
    const int lane = tid & 31;
    const int warp_m = wid & 1;
    const int warp_n = wid >> 1;
    const int m0 = blockIdx.y * 128;
    const int n0 = blockIdx.x * GEMM_BN;
    const u32 sbase = smem_u32(buf);
    const size_t strideB = (size_t)Keff * 2;
    const int niter = Keff / 32;

    float c[4][6][4];
#pragma unroll
    for (int i = 0; i < 4; ++i)
#pragma unroll
        for (int j = 0; j < 6; ++j)
#pragma unroll
            for (int q = 0; q < 4; ++q) c[i][j][q] = 0.f;

    const int rowL = tid >> 2;
    const int uL   = tid & 3;

#pragma unroll
    for (int s = 0; s < 2; ++s) {
        u32 ab = sbase + s * GEMM_STAGE;
#pragma unroll
        for (int q = 0; q < 2; ++q) {
            int row = rowL + q * 64;
            int p = uL ^ ((row >> 1) & 3);
            cp_async16(ab + row * 64 + p * 16,
                       (const char*)A + (size_t)(m0 + row) * strideB + (size_t)s * 64 + uL * 16);
        }
#pragma unroll
        for (int q = 0; q < 3; ++q) {
            int row = rowL + q * 64;
            int p = uL ^ ((row >> 1) & 3);
            cp_async16(ab + 8192 + row * 64 + p * 16,
                       (const char*)W + (size_t)(n0 + row) * strideB + (size_t)s * 64 + uL * 16);
        }
        cp_commit();
    }

    for (int i = 0; i < niter; ++i) {
        cp_wait1();
        __syncthreads();

        if (i + 2 < niter) {
            u32 ab = sbase + ((i + 2) % 3) * GEMM_STAGE;
#pragma unroll
            for (int q = 0; q < 2; ++q) {
                int row = rowL + q * 64;
                int p = uL ^ ((row >> 1) & 3);
                cp_async16(ab + row * 64 + p * 16,
                           (const char*)A + (size_t)(m0 + row) * strideB + (size_t)(i + 2) * 64 + uL * 16);
            }
#pragma unroll
            for (int q = 0; q < 3; ++q) {
                int row = rowL + q * 64;
                int p = uL ^ ((row >> 1) & 3);
                cp_async16(ab + 8192 + row * 64 + p * 16,
                           (const char*)W + (size_t)(n0 + row) * strideB + (size_t)(i + 2) * 64 + uL * 16);
            }
        }
        cp_commit();

        u32 abase = sbase + (i % 3) * GEMM_STAGE;
        u32 bbase = abase + 8192;
        const int mi = lane >> 3;
        const int rl = lane & 7;
#pragma unroll
        for (int h = 0; h < 2; ++h) {
            u32 afr[4][4];
#pragma unroll
            for (int mt = 0; mt < 4; ++mt) {
                int row = warp_m * 64 + mt * 16 + (mi & 1) * 8 + rl;
                int u = 2 * h + (mi >> 1);
                int p = u ^ ((row >> 1) & 3);
                ldsm_x4(afr[mt], abase + row * 64 + p * 16);
            }
            u32 bfr[6][2];
#pragma unroll
            for (int pp = 0; pp < 3; ++pp) {
                int j = pp * 2 + (mi >> 1);
                int row = warp_n * 48 + j * 8 + rl;
                int u = 2 * h + (mi & 1);
                int p = u ^ ((row >> 1) & 3);
                u32 r4[4];
                ldsm_x4(r4, bbase + row * 64 + p * 16);
                bfr[pp*2][0] = r4[0]; bfr[pp*2][1] = r4[1];
                bfr[pp*2+1][0] = r4[2]; bfr[pp*2+1][1] = r4[3];
            }
#pragma unroll
            for (int mt = 0; mt < 4; ++mt)
#pragma unroll
                for (int nt = 0; nt < 6; ++nt)
                    mma16816(c[mt][nt], afr[mt], bfr[nt]);
        }
        // trailing __syncthreads removed (see kernel comment)
    }

    const int mwb = m0 + warp_m * 64;
    const int nwb = n0 + warp_n * 48;
#pragma unroll
    for (int mt = 0; mt < 4; ++mt) {
#pragma unroll
        for (int nt = 0; nt < 6; ++nt) {
            int m = mwb + mt * 16 + (lane >> 2);
            int n = nwb + nt * 8 + (lane & 3) * 2;
            float bx = __ldg(bias + n), by = __ldg(bias + n + 1);
            float2 o0 = { c[mt][nt][0] + bx, c[mt][nt][1] + by };
            float2 o1 = { c[mt][nt][2] + bx, c[mt][nt][3] + by };
            *(float2*)(C + (size_t)m * G3 + n) = o0;
            *(float2*)(C + (size_t)(m + 8) * G3 + n) = o1;
        }
    }
}

// =====================================================================
// grid barrier — proven flat atomic/volatile protocol (gen-relative)
// =====================================================================
__device__ __forceinline__ void grid_barrier_dev() {
    __syncthreads();
    if (threadIdx.x == 0) {
        __threadfence();
        unsigned gen = g_gen;
        if (atomicAdd(&g_count, 1u) == (unsigned)(gridDim.x - 1)) {
            g_count = 0;
            __threadfence();
            g_gen = gen + 1;
        } else {
            while (g_gen == gen) { }
        }
        __threadfence();
    }
    __syncthreads();
}

// =====================================================================
// Tensor-core GRU recurrence v5: fragment-direct h exchange +
// register-resident weight fragments + gates prefetch (R14) +
// R15: h-image stores packed pairwise via shfl into 4B words
// (lanes l and l+16 own the two bf16 halves of one fragment word).
// SMEM: w_hi 0..48K | w_lo 48K..96K | red 96K..108K
// =====================================================================
#define RCTA 128
#define WHI_OFF 0
#define WLO_OFF 49152
#define RED_OFF 98304
#define REC_SMEM_TC 110592

__global__ void __launch_bounds__(256, 1) gru_rec_tc(
    const float* __restrict__ w_hh, const float* __restrict__ b_hh,
    const float* __restrict__ gates,
    unsigned short* __restrict__ acvt_out, float* __restrict__ hlast,
    int write_seq)
{
    extern __shared__ __align__(1024) char sm[];
    const u32 sb = smem_u32(sm);

    const int tid  = threadIdx.x;
    const int wid  = tid >> 5;
    const int lane = tid & 31;
    const int mi = lane >> 3;
    const int rl = lane & 7;
    const int ubase = blockIdx.x * 8;

    // ---- convert w_hh slice to split bf16 in SMEM (once) ----
    for (int idx = tid; idx < 24 * 128; idx += 256) {
        int r = idx >> 7;
        int q = idx & 127;
        int ulcl = r / 3, g = r - ulcl * 3;
        const float4* src = (const float4*)(w_hh + (size_t)(g * HH + ubase + ulcl) * HH + q * 8);
        float4 f0 = __ldg(src), f1 = __ldg(src + 1);
        uint4 hiw, low;
        cvt8_split(f0, f1, hiw, low);
        int c = q >> 2, u = q & 3;
        u32 off = (u32)(c * 1536 + r * 64 + ((u ^ ((r >> 1) & 3)) << 4));
        *(uint4*)(sm + WHI_OFF + off) = hiw;
        *(uint4*)(sm + WLO_OFF + off) = low;
    }
    __syncthreads();   // weights visible to all warps BEFORE first ldsm

    // ---- hoist B (weight) fragments into registers: 96 u32/thread ----
    u32 breg[8][12];
#pragma unroll
    for (int cc = 0; cc < 4; ++cc) {
        int ch = wid * 4 + cc;
        u32 wa = sb + WHI_OFF + ch * 1536;
        u32 wl = sb + WLO_OFF + ch * 1536;
#pragma unroll
        for (int h2 = 0; h2 < 2; ++h2) {
            int idx = cc * 2 + h2;
            int b01row = ((mi >> 1) << 3) + rl;
            int bu = 2 * h2 + (mi & 1);
            u32 b01off = (u32)(b01row * 64 + ((bu ^ ((b01row >> 1) & 3)) << 4));
            int b2row = 16 + rl;
            u32 b2off = (u32)(b2row * 64 + ((bu ^ ((b2row >> 1) & 3)) << 4));
            u32 bh01[4], bh2[4], bl01[4], bl2[4];
            ldsm_x4(bh01, wa + b01off);
            ldsm_x4(bh2,  wa + b2off);
            ldsm_x4(bl01, wl + b01off);
            ldsm_x4(bl2,  wl + b2off);
            breg[idx][0]  = bh01[0]; breg[idx][1]  = bh01[1];
            breg[idx][2]  = bh01[2]; breg[idx][3]  = bh01[3];
            breg[idx][4]  = bh2[0];  breg[idx][5]  = bh2[1];
            breg[idx][6]  = bl01[0]; breg[idx][7]  = bl01[1];
            breg[idx][8]  = bl01[2]; breg[idx][9]  = bl01[3];
            breg[idx][10] = bl2[0];  breg[idx][11] = bl2[1];
        }
    }

    // ---- epilogue constants ----
    const int ul_ep = tid >> 4;       // 0..7 local unit (tid<128)
    const int b_ep  = tid & 15;       // batch
    const int u_ep  = ubase + ul_ep;  // global unit = k index
    float bhr = 0.f, bhz = 0.f, bhn = 0.f;
    if (tid < 128) {
        bhr = b_hh[u_ep];
        bhz = b_hh[HH + u_ep];
        bhn = b_hh[2 * HH + u_ep];
    }
    const int kk_ep = u_ep & 15;
    const u32 my_off = (u32)((u_ep >> 4) * 512 +
                             ((b_ep & 7) * 4 + ((kk_ep & 7) >> 1)) * 16 +
                             (((b_ep >> 3) & 1) | ((kk_ep >> 3) << 1)) * 4 +
                             (kk_ep & 1) * 2);
    float hp = 0.f;

    const float* red = (const float*)(sm + RED_OFF);

    // ---- gates prefetch for t=0 ----
    float gxr = 0.f, gxz = 0.f, gxn = 0.f;
    if (tid < 128) {
        const float* gp = gates + (size_t)(b_ep * TT) * G3 + u_ep;
        gxr = __ldg(gp);
        gxz = __ldg(gp + HH);
        gxn = __ldg(gp + 2 * HH);
    }

    for (int t = 0; t < TT; ++t) {
        const char* img = (const char*)g_img[t & 1];

        // ---- mma phase: A from global fragment image, B from registers ----
        float cacc[3][4];
#pragma unroll
        for (int nt = 0; nt < 3; ++nt)
#pragma unroll
            for (int q = 0; q < 4; ++q) cacc[nt][q] = 0.f;

#pragma unroll
        for (int cc = 0; cc < 4; ++cc) {
#pragma unroll
            for (int h2 = 0; h2 < 2; ++h2) {
                int idx = cc * 2 + h2;
                int c16 = (wid * 4 + cc) * 2 + h2;
                const char* pa = img + c16 * 512 + lane * 16;
                u32 ahi[4], alo[4];
                ld4cg(ahi, pa);
                ld4cg(alo, pa + 32768);

                mma16816(cacc[0], ahi, &breg[idx][0]);
                mma16816(cacc[1], ahi, &breg[idx][2]);
                mma16816(cacc[2], ahi, &breg[idx][4]);
                mma16816(cacc[0], alo, &breg[idx][0]);
                mma16816(cacc[1], alo, &breg[idx][2]);
                mma16816(cacc[2], alo, &breg[idx][4]);
                mma16816(cacc[0], ahi, &breg[idx][6]);
                mma16816(cacc[1], ahi, &breg[idx][8]);
                mma16816(cacc[2], ahi, &breg[idx][10]);
            }
        }

        // ---- store partial frags, reduce across 8 warps ----
#pragma unroll
        for (int nt = 0; nt < 3; ++nt) {
            float4 v = { cacc[nt][0], cacc[nt][1], cacc[nt][2], cacc[nt][3] };
            *(float4*)(sm + RED_OFF + (size_t)(((wid * 3 + nt) * 32 + lane) << 4)) = v;
        }
        __syncthreads();

        // ---- epilogue ----
        if (tid < 128) {
            float gh[3];
#pragma unroll
            for (int g = 0; g < 3; ++g) {
                int j = ul_ep * 3 + g;
                int tile = j >> 3;
                int col = j & 7;
                int ln = (b_ep & 7) * 4 + (col >> 1);
                int rg = (col & 1) + 2 * (b_ep >> 3);
                float s = 0.f;
#pragma unroll
                for (int w8 = 0; w8 < 8; ++w8)
                    s += red[((w8 * 3 + tile) * 32 + ln) * 4 + rg];
                gh[g] = s;
            }
            float rr = 1.f / (1.f + __expf(-(gxr + gh[0] + bhr)));
            float zz = 1.f / (1.f + __expf(-(gxz + gh[1] + bhz)));
            float nn = tanhf(gxn + rr * (gh[2] + bhn));
            float hv = (1.f - zz) * nn + zz * hp;
            hp = hv;

            // split to bf16 hi/lo
            __nv_bfloat16 hb = __float2bfloat16(hv);
            __nv_bfloat16 lb = __float2bfloat16(hv - __bfloat162float(hb));
            unsigned short hs = *(unsigned short*)&hb;
            unsigned short ls = *(unsigned short*)&lb;

            // pack pairwise: lane l (kk even) and lane l+16 (kk odd) of the
            // same warp own the two halves of one 4B fragment word
            u32 hs32 = (u32)hs, ls32 = (u32)ls;
            u32 hs_up = __shfl_down_sync(0xffffffffu, hs32, 16);
            u32 ls_up = __shfl_down_sync(0xffffffffu, ls32, 16);
            unsigned char* imgd = g_img[(t + 1) & 1];
            if (lane < 16) {
                u32 hword = hs32 | (hs_up << 16);
                u32 lword = ls32 | (ls_up << 16);
                asm volatile("st.global.cg.b32 [%0], %1;" :: "l"(imgd + my_off), "r"(hword) : "memory");
                asm volatile("st.global.cg.b32 [%0], %1;" :: "l"(imgd + 32768 + my_off), "r"(lword) : "memory");
            }

            if (write_seq) {
                unsigned short* arow = acvt_out + ((size_t)(b_ep * TT + t) * 3 * HH + 3 * u_ep);
                asm volatile("st.global.cg.b16 [%0], %1;" :: "l"(arow),     "h"(hs) : "memory");
                asm volatile("st.global.cg.b16 [%0], %1;" :: "l"(arow + 1), "h"(ls) : "memory");
                asm volatile("st.global.cg.b16 [%0], %1;" :: "l"(arow + 2), "h"(hs) : "memory");
            }
            if (t == TT - 1)
                hlast[b_ep * HH + u_ep] = hv;

            // prefetch next step's gates (latency hides under the barrier)
            if (t + 1 < TT) {
                const float* gp = gates + (size_t)(b_ep * TT + t + 1) * G3 + u_ep;
                gxr = __ldg(gp);
                gxz = __ldg(gp + HH);
                gxn = __ldg(gp + 2 * HH);
            }
        }

        if (t + 1 < TT) grid_barrier_dev();
    }
}

// =====================================================================
// Decoder (unchanged)
// =====================================================================
__global__ void __launch_bounds__(256) decoder_kernel(
    const float* __restrict__ h, const float* __restrict__ dw,
    const float* __restrict__ db, float* __restrict__ out)
{
    extern __shared__ __align__(16) float sh[];
    const int tid = threadIdx.x;
    for (int i = tid; i < BQ * HH / 4; i += 256)
        ((float4*)sh)[i] = ((const float4*)h)[i];
    __syncthreads();

    const int w = tid >> 5, lane = tid & 31;
#pragma unroll 1
    for (int i = 0; i < 4; ++i) {
        int n = blockIdx.x * 32 + w * 4 + i;
        float acc[16];
#pragma unroll
        for (int b = 0; b < 16; ++b) acc[b] = 0.f;
#pragma unroll
        for (int it = 0; it < 8; ++it) {
            int kq = it * 32 + lane;
            float4 wv = __ldg(((const float4*)(dw + (size_t)n * HH)) + kq);
#pragma unroll
            for (int b = 0; b < 16; ++b) {
                float4 hv = *(((const float4*)(sh + b * HH)) + kq);
                acc[b] += wv.x * hv.x + wv.y * hv.y + wv.z * hv.z + wv.w * hv.w;
            }
        }
        float myv = 0.f;
#pragma unroll
        for (int b = 0; b < 16; ++b) {
            float v = acc[b];
            v += __shfl_xor_sync(0xffffffffu, v, 16);
            v += __shfl_xor_sync(0xffffffffu, v, 8);
            v += __shfl_xor_sync(0xffffffffu, v, 4);
            v += __shfl_xor_sync(0xffffffffu, v, 2);
            v += __shfl_xor_sync(0xffffffffu, v, 1);
            if (lane == b) myv = v;
        }
        if (lane < 16) out[(size_t)lane * NNDIM + n] = myv + __ldg(db + n);
    }
}

// =====================================================================
extern "C" void kernel_launch(void* const* d_in, const int* in_sizes, int n_in,
                              void* d_out, int out_size)
{
    const float* x      = (const float*)d_in[0];
    const float* w_ih0  = (const float*)d_in[1];
    const float* w_hh0  = (const float*)d_in[2];
    const float* b_ih0  = (const float*)d_in[3];
    const float* b_hh0  = (const float*)d_in[4];
    const float* w_ih1  = (const float*)d_in[5];
    const float* w_hh1  = (const float*)d_in[6];
    const float* b_ih1  = (const float*)d_in[7];
    const float* b_hh1  = (const float*)d_in[8];
    const float* dec_w  = (const float*)d_in[9];
    const float* dec_b  = (const float*)d_in[10];
    float* out = (float*)d_out;

    float *gates, *hbuf;
    unsigned short *wcvt, *acvt;
    cudaGetSymbolAddress((void**)&gates, g_gates);
    cudaGetSymbolAddress((void**)&hbuf,  g_hbuf);
    cudaGetSymbolAddress((void**)&wcvt,  g_wcvt);
    cudaGetSymbolAddress((void**)&acvt,  g_acvt);

    cudaFuncSetAttribute(gemm_bf16_tc,
                         cudaFuncAttributeMaxDynamicSharedMemorySize, GEMM_SMEM);
    cudaFuncSetAttribute(gru_rec_tc,
                         cudaFuncAttributeMaxDynamicSharedMemorySize, REC_SMEM_TC);
    cudaFuncSetAttribute(decoder_kernel,
                         cudaFuncAttributeMaxDynamicSharedMemorySize, BQ * HH * 4);

    dim3 ggrid(G3 / GEMM_BN, (BQ * TT) / 128);   // (16, 8) = 128 CTAs, one wave

    // ---- layer 0 ----
    {
        int K = NNDIM;
        int totW = G3 * (K / 8), totA = BQ * TT * (K / 8);
        conv_split_rm<<<(totW + 255) / 256, 256>>>(w_ih0, wcvt, K, totW, 0, 0);
        conv_split_rm<<<(totA + 255) / 256, 256>>>(x,     acvt, K, totA, 1, 1);  // + zero g_img[0]
        gemm_bf16_tc<<<ggrid, 256, GEMM_SMEM>>>(acvt, wcvt, b_ih0, gates, 3 * K);
    }
    gru_rec_tc<<<RCTA, 256, REC_SMEM_TC>>>(w_hh0, b_hh0, gates, acvt, hbuf, 1);

    // ---- layer 1 (A rows written by layer-0 epilogue) ----
    {
        int K = HH;
        int totW = G3 * (K / 8);
        conv_split_rm<<<(totW + 255) / 256, 256>>>(w_ih1, wcvt, K, totW, 0, 1);  // + zero g_img[0]
        gemm_bf16_tc<<<ggrid, 256, GEMM_SMEM>>>(acvt, wcvt, b_ih1, gates, 3 * K);
    }
    gru_rec_tc<<<RCTA, 256, REC_SMEM_TC>>>(w_hh1, b_hh1, gates, acvt, hbuf, 0);

    // ---- decoder ----
    decoder_kernel<<<NNDIM / 32, 256, BQ * HH * 4>>>(hbuf, dec_w, dec_b, out);
}

// round 16
// speedup vs baseline: 1.0150x; 1.0150x over previous
#include <cuda_runtime.h>
#include <cuda_bf16.h>
#include <math.h>

#define BQ 16
#define TT 64
#define HH 1024
#define NNDIM 4096
#define G3 3072

typedef unsigned long long u64;
typedef unsigned int u32;

// ---------- device scratch ----------
__device__ float g_gates[BQ * TT * G3];
__device__ float g_hbuf[BQ * HH];                        // final h for decoder
// h image, mma-A-fragment layout: [c16 chunk 0..63][lane 0..31][reg 0..3][half]
// hi at [0,32KB), lo at [32KB,64KB). Two ping-pong buffers.
__device__ __align__(16) unsigned char g_img[2][65536];
__device__ unsigned g_count = 0;
__device__ volatile unsigned g_gen = 0;
__device__ unsigned short g_wcvt[(size_t)G3 * 3 * NNDIM];
__device__ unsigned short g_acvt[(size_t)BQ * TT * 3 * NNDIM];

__device__ __forceinline__ u32 smem_u32(const void* p) {
    u32 a; asm("{ .reg .u64 t; cvta.to.shared.u64 t, %1; cvt.u32.u64 %0, t; }" : "=r"(a) : "l"(p));
    return a;
}
__device__ __forceinline__ void cp_async16(u32 dst, const void* src) {
    asm volatile("cp.async.cg.shared.global [%0], [%1], 16;" :: "r"(dst), "l"(src) : "memory");
}
__device__ __forceinline__ void cp_commit() {
    asm volatile("cp.async.commit_group;" ::: "memory");
}
__device__ __forceinline__ void cp_wait1() {
    asm volatile("cp.async.wait_group 1;" ::: "memory");
}
__device__ __forceinline__ void ldsm_x4(u32* r, u32 addr) {
    asm volatile("ldmatrix.sync.aligned.m8n8.x4.shared.b16 {%0,%1,%2,%3}, [%4];"
                 : "=r"(r[0]), "=r"(r[1]), "=r"(r[2]), "=r"(r[3]) : "r"(addr));
}
__device__ __forceinline__ void ld4cg(u32* r, const void* p) {
    asm volatile("ld.global.cg.v4.u32 {%0,%1,%2,%3}, [%4];"
                 : "=r"(r[0]), "=r"(r[1]), "=r"(r[2]), "=r"(r[3]) : "l"(p));
}
__device__ __forceinline__ void mma16816(float* c, const u32* a, const u32* b) {
    asm volatile(
        "mma.sync.aligned.m16n8k16.row.col.f32.bf16.bf16.f32 "
        "{%0,%1,%2,%3}, {%4,%5,%6,%7}, {%8,%9}, {%0,%1,%2,%3};"
        : "+f"(c[0]), "+f"(c[1]), "+f"(c[2]), "+f"(c[3])
        : "r"(a[0]), "r"(a[1]), "r"(a[2]), "r"(a[3]), "r"(b[0]), "r"(b[1]));
}

// hi/lo split of 8 floats -> two packed uint4 of bf16
__device__ __forceinline__ void cvt8_split(float4 f0, float4 f1, uint4& hiw, uint4& low) {
    float v[8] = { f0.x, f0.y, f0.z, f0.w, f1.x, f1.y, f1.z, f1.w };
    unsigned short h[8], l[8];
#pragma unroll
    for (int k = 0; k < 8; ++k) {
        __nv_bfloat16 hb = __float2bfloat16(v[k]);
        __nv_bfloat16 lb = __float2bfloat16(v[k] - __bfloat162float(hb));
        h[k] = *(unsigned short*)&hb;
        l[k] = *(unsigned short*)&lb;
    }
    hiw.x = (u32)h[0] | ((u32)h[1] << 16); hiw.y = (u32)h[2] | ((u32)h[3] << 16);
    hiw.z = (u32)h[4] | ((u32)h[5] << 16); hiw.w = (u32)h[6] | ((u32)h[7] << 16);
    low.x = (u32)l[0] | ((u32)l[1] << 16); low.y = (u32)l[2] | ((u32)l[3] << 16);
    low.z = (u32)l[4] | ((u32)l[5] << 16); low.w = (u32)l[6] | ((u32)l[7] << 16);
}

// =====================================================================
// conv_split_rm: fp32 [rows, K] -> split-bf16 row-major [rows, 3K]
// rz=1: first 16 blocks additionally zero g_img[0].
// =====================================================================
__global__ void conv_split_rm(const float* __restrict__ src, unsigned short* __restrict__ dst,
                              int K, int total, int a_mode, int rz)
{
    if (rz && blockIdx.x < 16) {
        int i = blockIdx.x * 256 + threadIdx.x;
        if (i < 4096) ((uint4*)g_img[0])[i] = make_uint4(0u, 0u, 0u, 0u);
    }
    int t = blockIdx.x * blockDim.x + threadIdx.x;
    if (t >= total) return;
    int kg = t % (K >> 3);
    int r  = t / (K >> 3);
    const float4* p = (const float4*)(src + (size_t)r * K + kg * 8);
    float v[8];
    float4 f0 = __ldg(p), f1 = __ldg(p + 1);
    v[0]=f0.x; v[1]=f0.y; v[2]=f0.z; v[3]=f0.w;
    v[4]=f1.x; v[5]=f1.y; v[6]=f1.z; v[7]=f1.w;
    unsigned short o[24];
#pragma unroll
    for (int k = 0; k < 8; ++k) {
        __nv_bfloat16 hi = __float2bfloat16(v[k]);
        __nv_bfloat16 lo = __float2bfloat16(v[k] - __bfloat162float(hi));
        unsigned short hs = *(unsigned short*)&hi;
        unsigned short ls = *(unsigned short*)&lo;
        o[3*k+0] = hs;
        o[3*k+1] = a_mode ? ls : hs;
        o[3*k+2] = a_mode ? hs : ls;
    }
    unsigned short* d = dst + (size_t)r * 3 * K + (size_t)kg * 24;
    ((uint4*)d)[0] = ((uint4*)o)[0];
    ((uint4*)d)[1] = ((uint4*)o)[1];
    ((uint4*)d)[2] = ((uint4*)o)[2];
}

// =====================================================================
// bf16 tensor-core GEMM: CTA 128x192, one wave (16x8 grid).
// Single __syncthreads per k-iteration (R15-validated: loads for stage
// i+2 are issued after the top sync of iter i, which already guarantees
// all warps finished compute of iter i-1, the only reader of that buffer).
// =====================================================================
#define GEMM_BN 192
#define GEMM_STAGE 20480
#define GEMM_SMEM (3 * GEMM_STAGE)

__global__ void __launch_bounds__(256, 1) gemm_bf16_tc(
    const unsigned short* __restrict__ A, const unsigned short* __restrict__ W,
    const float* __restrict__ bias, float* __restrict__ C, int Keff)
{
    extern __shared__ __align__(1024) char buf[];

    const int tid  = threadIdx.x;
    const int wid  = tid >> 5;
    const int lane = tid & 31;
    const int warp_m = wid & 1;
    const int warp_n = wid >> 1;
    const int m0 = blockIdx.y * 128;
    const int n0 = blockIdx.x * GEMM_BN;
    const u32 sbase = smem_u32(buf);
    const size_t strideB = (size_t)Keff * 2;
    const int niter = Keff / 32;

    float c[4][6][4];
#pragma unroll
    for (int i = 0; i < 4; ++i)
#pragma unroll
        for (int j = 0; j < 6; ++j)
#pragma unroll
            for (int q = 0; q < 4; ++q) c[i][j][q] = 0.f;

    const int rowL = tid >> 2;
    const int uL   = tid & 3;

#pragma unroll
    for (int s = 0; s < 2; ++s) {
        u32 ab = sbase + s * GEMM_STAGE;
#pragma unroll
        for (int q = 0; q < 2; ++q) {
            int row = rowL + q * 64;
            int p = uL ^ ((row >> 1) & 3);
            cp_async16(ab + row * 64 + p * 16,
                       (const char*)A + (size_t)(m0 + row) * strideB + (size_t)s * 64 + uL * 16);
        }
#pragma unroll
        for (int q = 0; q < 3; ++q) {
            int row = rowL + q * 64;
            int p = uL ^ ((row >> 1) & 3);
            cp_async16(ab + 8192 + row * 64 + p * 16,
                       (const char*)W + (size_t)(n0 + row) * strideB + (size_t)s * 64 + uL * 16);
        }
        cp_commit();
    }

    for (int i = 0; i < niter; ++i) {
        cp_wait1();
        __syncthreads();

        if (i + 2 < niter) {
            u32 ab = sbase + ((i + 2) % 3) * GEMM_STAGE;
#pragma unroll
            for (int q = 0; q < 2; ++q) {
                int row = rowL + q * 64;
                int p = uL ^ ((row >> 1) & 3);
                cp_async16(ab + row * 64 + p * 16,
                           (const char*)A + (size_t)(m0 + row) * strideB + (size_t)(i + 2) * 64 + uL * 16);
            }
#pragma unroll
            for (int q = 0; q < 3; ++q) {
                int row = rowL + q * 64;
                int p = uL ^ ((row >> 1) & 3);
                cp_async16(ab + 8192 + row * 64 + p * 16,
                           (const char*)W + (size_t)(n0 + row) * strideB + (size_t)(i + 2) * 64 + uL * 16);
            }
        }
        cp_commit();

        u32 abase = sbase + (i % 3) * GEMM_STAGE;
        u32 bbase = abase + 8192;
        const int mi = lane >> 3;
        const int rl = lane & 7;
#pragma unroll
        for (int h = 0; h < 2; ++h) {
            u32 afr[4][4];
#pragma unroll
            for (int mt = 0; mt < 4; ++mt) {
                int row = warp_m * 64 + mt * 16 + (mi & 1) * 8 + rl;
                int u = 2 * h + (mi >> 1);
                int p = u ^ ((row >> 1) & 3);
                ldsm_x4(afr[mt], abase + row * 64 + p * 16);
            }
            u32 bfr[6][2];
#pragma unroll
            for (int pp = 0; pp < 3; ++pp) {
                int j = pp * 2 + (mi >> 1);
                int row = warp_n * 48 + j * 8 + rl;
                int u = 2 * h + (mi & 1);
                int p = u ^ ((row >> 1) & 3);
                u32 r4[4];
                ldsm_x4(r4, bbase + row * 64 + p * 16);
                bfr[pp*2][0] = r4[0]; bfr[pp*2][1] = r4[1];
                bfr[pp*2+1][0] = r4[2]; bfr[pp*2+1][1] = r4[3];
            }
#pragma unroll
            for (int mt = 0; mt < 4; ++mt)
#pragma unroll
                for (int nt = 0; nt < 6; ++nt)
                    mma16816(c[mt][nt], afr[mt], bfr[nt]);
        }
    }

    const int mwb = m0 + warp_m * 64;
    const int nwb = n0 + warp_n * 48;
#pragma unroll
    for (int mt = 0; mt < 4; ++mt) {
#pragma unroll
        for (int nt = 0; nt < 6; ++nt) {
            int m = mwb + mt * 16 + (lane >> 2);
            int n = nwb + nt * 8 + (lane & 3) * 2;
            float bx = __ldg(bias + n), by = __ldg(bias + n + 1);
            float2 o0 = { c[mt][nt][0] + bx, c[mt][nt][1] + by };
            float2 o1 = { c[mt][nt][2] + bx, c[mt][nt][3] + by };
            *(float2*)(C + (size_t)m * G3 + n) = o0;
            *(float2*)(C + (size_t)(m + 8) * G3 + n) = o1;
        }
    }
}

// =====================================================================
// grid barrier — proven flat atomic/volatile protocol (gen-relative)
// =====================================================================
__device__ __forceinline__ void grid_barrier_dev() {
    __syncthreads();
    if (threadIdx.x == 0) {
        __threadfence();
        unsigned gen = g_gen;
        if (atomicAdd(&g_count, 1u) == (unsigned)(gridDim.x - 1)) {
            g_count = 0;
            __threadfence();
            g_gen = gen + 1;
        } else {
            while (g_gen == gen) { }
        }
        __threadfence();
    }
    __syncthreads();
}

// =====================================================================
// Tensor-core GRU recurrence (R14 exact — best measured: 279.6us):
// fragment-direct h exchange + register-resident weight fragments +
// gates prefetched one step ahead. Plain b16 image stores (shfl-packed
// variant measured slower in R15).
// SMEM: w_hi 0..48K | w_lo 48K..96K | red 96K..108K
// =====================================================================
#define RCTA 128
#define WHI_OFF 0
#define WLO_OFF 49152
#define RED_OFF 98304
#define REC_SMEM_TC 110592

__global__ void __launch_bounds__(256, 1) gru_rec_tc(
    const float* __restrict__ w_hh, const float* __restrict__ b_hh,
    const float* __restrict__ gates,
    unsigned short* __restrict__ acvt_out, float* __restrict__ hlast,
    int write_seq)
{
    extern __shared__ __align__(1024) char sm[];
    const u32 sb = smem_u32(sm);

    const int tid  = threadIdx.x;
    const int wid  = tid >> 5;
    const int lane = tid & 31;
    const int mi = lane >> 3;
    const int rl = lane & 7;
    const int ubase = blockIdx.x * 8;

    // ---- convert w_hh slice to split bf16 in SMEM (once) ----
    for (int idx = tid; idx < 24 * 128; idx += 256) {
        int r = idx >> 7;
        int q = idx & 127;
        int ulcl = r / 3, g = r - ulcl * 3;
        const float4* src = (const float4*)(w_hh + (size_t)(g * HH + ubase + ulcl) * HH + q * 8);
        float4 f0 = __ldg(src), f1 = __ldg(src + 1);
        uint4 hiw, low;
        cvt8_split(f0, f1, hiw, low);
        int c = q >> 2, u = q & 3;
        u32 off = (u32)(c * 1536 + r * 64 + ((u ^ ((r >> 1) & 3)) << 4));
        *(uint4*)(sm + WHI_OFF + off) = hiw;
        *(uint4*)(sm + WLO_OFF + off) = low;
    }
    __syncthreads();   // weights visible to all warps BEFORE first ldsm

    // ---- hoist B (weight) fragments into registers: 96 u32/thread ----
    u32 breg[8][12];
#pragma unroll
    for (int cc = 0; cc < 4; ++cc) {
        int ch = wid * 4 + cc;
        u32 wa = sb + WHI_OFF + ch * 1536;
        u32 wl = sb + WLO_OFF + ch * 1536;
#pragma unroll
        for (int h2 = 0; h2 < 2; ++h2) {
            int idx = cc * 2 + h2;
            int b01row = ((mi >> 1) << 3) + rl;
            int bu = 2 * h2 + (mi & 1);
            u32 b01off = (u32)(b01row * 64 + ((bu ^ ((b01row >> 1) & 3)) << 4));
            int b2row = 16 + rl;
            u32 b2off = (u32)(b2row * 64 + ((bu ^ ((b2row >> 1) & 3)) << 4));
            u32 bh01[4], bh2[4], bl01[4], bl2[4];
            ldsm_x4(bh01, wa + b01off);
            ldsm_x4(bh2,  wa + b2off);
            ldsm_x4(bl01, wl + b01off);
            ldsm_x4(bl2,  wl + b2off);
            breg[idx][0]  = bh01[0]; breg[idx][1]  = bh01[1];
            breg[idx][2]  = bh01[2]; breg[idx][3]  = bh01[3];
            breg[idx][4]  = bh2[0];  breg[idx][5]  = bh2[1];
            breg[idx][6]  = bl01[0]; breg[idx][7]  = bl01[1];
            breg[idx][8]  = bl01[2]; breg[idx][9]  = bl01[3];
            breg[idx][10] = bl2[0];  breg[idx][11] = bl2[1];
        }
    }

    // ---- epilogue constants ----
    const int ul_ep = tid >> 4;       // 0..7 local unit (tid<128)
    const int b_ep  = tid & 15;       // batch
    const int u_ep  = ubase + ul_ep;  // global unit = k index
    float bhr = 0.f, bhz = 0.f, bhn = 0.f;
    if (tid < 128) {
        bhr = b_hh[u_ep];
        bhz = b_hh[HH + u_ep];
        bhn = b_hh[2 * HH + u_ep];
    }
    const int kk_ep = u_ep & 15;
    const u32 my_off = (u32)((u_ep >> 4) * 512 +
                             ((b_ep & 7) * 4 + ((kk_ep & 7) >> 1)) * 16 +
                             (((b_ep >> 3) & 1) | ((kk_ep >> 3) << 1)) * 4 +
                             (kk_ep & 1) * 2);
    float hp = 0.f;

    const float* red = (const float*)(sm + RED_OFF);

    // ---- gates prefetch for t=0 ----
    float gxr = 0.f, gxz = 0.f, gxn = 0.f;
    if (tid < 128) {
        const float* gp = gates + (size_t)(b_ep * TT) * G3 + u_ep;
        gxr = __ldg(gp);
        gxz = __ldg(gp + HH);
        gxn = __ldg(gp + 2 * HH);
    }

    for (int t = 0; t < TT; ++t) {
        const char* img = (const char*)g_img[t & 1];

        // ---- mma phase: A from global fragment image, B from registers ----
        float cacc[3][4];
#pragma unroll
        for (int nt = 0; nt < 3; ++nt)
#pragma unroll
            for (int q = 0; q < 4; ++q) cacc[nt][q] = 0.f;

#pragma unroll
        for (int cc = 0; cc < 4; ++cc) {
#pragma unroll
            for (int h2 = 0; h2 < 2; ++h2) {
                int idx = cc * 2 + h2;
                int c16 = (wid * 4 + cc) * 2 + h2;
                const char* pa = img + c16 * 512 + lane * 16;
                u32 ahi[4], alo[4];
                ld4cg(ahi, pa);
                ld4cg(alo, pa + 32768);

                mma16816(cacc[0], ahi, &breg[idx][0]);
                mma16816(cacc[1], ahi, &breg[idx][2]);
                mma16816(cacc[2], ahi, &breg[idx][4]);
                mma16816(cacc[0], alo, &breg[idx][0]);
                mma16816(cacc[1], alo, &breg[idx][2]);
                mma16816(cacc[2], alo, &breg[idx][4]);
                mma16816(cacc[0], ahi, &breg[idx][6]);
                mma16816(cacc[1], ahi, &breg[idx][8]);
                mma16816(cacc[2], ahi, &breg[idx][10]);
            }
        }

        // ---- store partial frags, reduce across 8 warps ----
#pragma unroll
        for (int nt = 0; nt < 3; ++nt) {
            float4 v = { cacc[nt][0], cacc[nt][1], cacc[nt][2], cacc[nt][3] };
            *(float4*)(sm + RED_OFF + (size_t)(((wid * 3 + nt) * 32 + lane) << 4)) = v;
        }
        __syncthreads();

        // ---- epilogue ----
        if (tid < 128) {
            float gh[3];
#pragma unroll
            for (int g = 0; g < 3; ++g) {
                int j = ul_ep * 3 + g;
                int tile = j >> 3;
                int col = j & 7;
                int ln = (b_ep & 7) * 4 + (col >> 1);
                int rg = (col & 1) + 2 * (b_ep >> 3);
                float s = 0.f;
#pragma unroll
                for (int w8 = 0; w8 < 8; ++w8)
                    s += red[((w8 * 3 + tile) * 32 + ln) * 4 + rg];
                gh[g] = s;
            }
            float rr = 1.f / (1.f + __expf(-(gxr + gh[0] + bhr)));
            float zz = 1.f / (1.f + __expf(-(gxz + gh[1] + bhz)));
            float nn = tanhf(gxn + rr * (gh[2] + bhn));
            float hv = (1.f - zz) * nn + zz * hp;
            hp = hv;

            // write split-bf16 h into next step's image (fragment layout)
            __nv_bfloat16 hb = __float2bfloat16(hv);
            __nv_bfloat16 lb = __float2bfloat16(hv - __bfloat162float(hb));
            unsigned short hs = *(unsigned short*)&hb;
            unsigned short ls = *(unsigned short*)&lb;
            unsigned char* imgd = g_img[(t + 1) & 1];
            asm volatile("st.global.cg.b16 [%0], %1;" :: "l"(imgd + my_off), "h"(hs) : "memory");
            asm volatile("st.global.cg.b16 [%0], %1;" :: "l"(imgd + 32768 + my_off), "h"(ls) : "memory");

            if (write_seq) {
                unsigned short* arow = acvt_out + ((size_t)(b_ep * TT + t) * 3 * HH + 3 * u_ep);
                asm volatile("st.global.cg.b16 [%0], %1;" :: "l"(arow),     "h"(hs) : "memory");
                asm volatile("st.global.cg.b16 [%0], %1;" :: "l"(arow + 1), "h"(ls) : "memory");
                asm volatile("st.global.cg.b16 [%0], %1;" :: "l"(arow + 2), "h"(hs) : "memory");
            }
            if (t == TT - 1)
                hlast[b_ep * HH + u_ep] = hv;

            // prefetch next step's gates (latency hides under the barrier)
            if (t + 1 < TT) {
                const float* gp = gates + (size_t)(b_ep * TT + t + 1) * G3 + u_ep;
                gxr = __ldg(gp);
                gxz = __ldg(gp + HH);
                gxn = __ldg(gp + 2 * HH);
            }
        }

        if (t + 1 < TT) grid_barrier_dev();
    }
}

// =====================================================================
// Decoder (unchanged)
// =====================================================================
__global__ void __launch_bounds__(256) decoder_kernel(
    const float* __restrict__ h, const float* __restrict__ dw,
    const float* __restrict__ db, float* __restrict__ out)
{
    extern __shared__ __align__(16) float sh[];
    const int tid = threadIdx.x;
    for (int i = tid; i < BQ * HH / 4; i += 256)
        ((float4*)sh)[i] = ((const float4*)h)[i];
    __syncthreads();

    const int w = tid >> 5, lane = tid & 31;
#pragma unroll 1
    for (int i = 0; i < 4; ++i) {
        int n = blockIdx.x * 32 + w * 4 + i;
        float acc[16];
#pragma unroll
        for (int b = 0; b < 16; ++b) acc[b] = 0.f;
#pragma unroll
        for (int it = 0; it < 8; ++it) {
            int kq = it * 32 + lane;
            float4 wv = __ldg(((const float4*)(dw + (size_t)n * HH)) + kq);
#pragma unroll
            for (int b = 0; b < 16; ++b) {
                float4 hv = *(((const float4*)(sh + b * HH)) + kq);
                acc[b] += wv.x * hv.x + wv.y * hv.y + wv.z * hv.z + wv.w * hv.w;
            }
        }
        float myv = 0.f;
#pragma unroll
        for (int b = 0; b < 16; ++b) {
            float v = acc[b];
            v += __shfl_xor_sync(0xffffffffu, v, 16);
            v += __shfl_xor_sync(0xffffffffu, v, 8);
            v += __shfl_xor_sync(0xffffffffu, v, 4);
            v += __shfl_xor_sync(0xffffffffu, v, 2);
            v += __shfl_xor_sync(0xffffffffu, v, 1);
            if (lane == b) myv = v;
        }
        if (lane < 16) out[(size_t)lane * NNDIM + n] = myv + __ldg(db + n);
    }
}

// =====================================================================
extern "C" void kernel_launch(void* const* d_in, const int* in_sizes, int n_in,
                              void* d_out, int out_size)
{
    const float* x      = (const float*)d_in[0];
    const float* w_ih0  = (const float*)d_in[1];
    const float* w_hh0  = (const float*)d_in[2];
    const float* b_ih0  = (const float*)d_in[3];
    const float* b_hh0  = (const float*)d_in[4];
    const float* w_ih1  = (const float*)d_in[5];
    const float* w_hh1  = (const float*)d_in[6];
    const float* b_ih1  = (const float*)d_in[7];
    const float* b_hh1  = (const float*)d_in[8];
    const float* dec_w  = (const float*)d_in[9];
    const float* dec_b  = (const float*)d_in[10];
    float* out = (float*)d_out;

    float *gates, *hbuf;
    unsigned short *wcvt, *acvt;
    cudaGetSymbolAddress((void**)&gates, g_gates);
    cudaGetSymbolAddress((void**)&hbuf,  g_hbuf);
    cudaGetSymbolAddress((void**)&wcvt,  g_wcvt);
    cudaGetSymbolAddress((void**)&acvt,  g_acvt);

    cudaFuncSetAttribute(gemm_bf16_tc,
                         cudaFuncAttributeMaxDynamicSharedMemorySize, GEMM_SMEM);
    cudaFuncSetAttribute(gru_rec_tc,
                         cudaFuncAttributeMaxDynamicSharedMemorySize, REC_SMEM_TC);
    cudaFuncSetAttribute(decoder_kernel,
                         cudaFuncAttributeMaxDynamicSharedMemorySize, BQ * HH * 4);

    dim3 ggrid(G3 / GEMM_BN, (BQ * TT) / 128);   // (16, 8) = 128 CTAs, one wave

    // ---- layer 0 ----
    {
        int K = NNDIM;
        int totW = G3 * (K / 8), totA = BQ * TT * (K / 8);
        conv_split_rm<<<(totW + 255) / 256, 256>>>(w_ih0, wcvt, K, totW, 0, 0);
        conv_split_rm<<<(totA + 255) / 256, 256>>>(x,     acvt, K, totA, 1, 1);  // + zero g_img[0]
        gemm_bf16_tc<<<ggrid, 256, GEMM_SMEM>>>(acvt, wcvt, b_ih0, gates, 3 * K);
    }
    gru_rec_tc<<<RCTA, 256, REC_SMEM_TC>>>(w_hh0, b_hh0, gates, acvt, hbuf, 1);

    // ---- layer 1 (A rows written by layer-0 epilogue) ----
    {
        int K = HH;
        int totW = G3 * (K / 8);
        conv_split_rm<<<(totW + 255) / 256, 256>>>(w_ih1, wcvt, K, totW, 0, 1);  // + zero g_img[0]
        gemm_bf16_tc<<<ggrid, 256, GEMM_SMEM>>>(acvt, wcvt, b_ih1, gates, 3 * K);
    }
    gru_rec_tc<<<RCTA, 256, REC_SMEM_TC>>>(w_hh1, b_hh1, gates, acvt, hbuf, 0);

    // ---- decoder ----
    decoder_kernel<<<NNDIM / 32, 256, BQ * HH * 4>>>(hbuf, dec_w, dec_b, out);
}

// round 17
// speedup vs baseline: 1.1122x; 1.0957x over previous
#include <cuda_runtime.h>
#include <cuda_bf16.h>
#include <math.h>

#define BQ 16
#define TT 64
#define HH 1024
#define NNDIM 4096
#define G3 3072

typedef unsigned long long u64;
typedef unsigned int u32;

// ---------- device scratch ----------
__device__ float g_gates[BQ * TT * G3];
__device__ float g_hbuf[BQ * HH];                        // final h for decoder
// h image, mma-A-fragment layout (hi 32KB | lo 32KB), ping-pong
__device__ __align__(16) unsigned char g_img[2][65536];
__device__ unsigned g_count = 0;
__device__ volatile unsigned g_gen = 0;
// split planes: hi at [0, rows*K), lo at [rows*K, 2*rows*K)
__device__ unsigned short g_wcvt[(size_t)2 * G3 * NNDIM];        // 50 MB max
__device__ unsigned short g_acvt[(size_t)2 * BQ * TT * NNDIM];   // 16.8 MB max

__device__ __forceinline__ u32 smem_u32(const void* p) {
    u32 a; asm("{ .reg .u64 t; cvta.to.shared.u64 t, %1; cvt.u32.u64 %0, t; }" : "=r"(a) : "l"(p));
    return a;
}
__device__ __forceinline__ void cp_async16(u32 dst, const void* src) {
    asm volatile("cp.async.cg.shared.global [%0], [%1], 16;" :: "r"(dst), "l"(src) : "memory");
}
__device__ __forceinline__ void cp_commit() {
    asm volatile("cp.async.commit_group;" ::: "memory");
}
__device__ __forceinline__ void cp_wait1() {
    asm volatile("cp.async.wait_group 1;" ::: "memory");
}
__device__ __forceinline__ void ldsm_x4(u32* r, u32 addr) {
    asm volatile("ldmatrix.sync.aligned.m8n8.x4.shared.b16 {%0,%1,%2,%3}, [%4];"
                 : "=r"(r[0]), "=r"(r[1]), "=r"(r[2]), "=r"(r[3]) : "r"(addr));
}
__device__ __forceinline__ void ld4cg(u32* r, const void* p) {
    asm volatile("ld.global.cg.v4.u32 {%0,%1,%2,%3}, [%4];"
                 : "=r"(r[0]), "=r"(r[1]), "=r"(r[2]), "=r"(r[3]) : "l"(p));
}
__device__ __forceinline__ void mma16816(float* c, const u32* a, const u32* b) {
    asm volatile(
        "mma.sync.aligned.m16n8k16.row.col.f32.bf16.bf16.f32 "
        "{%0,%1,%2,%3}, {%4,%5,%6,%7}, {%8,%9}, {%0,%1,%2,%3};"
        : "+f"(c[0]), "+f"(c[1]), "+f"(c[2]), "+f"(c[3])
        : "r"(a[0]), "r"(a[1]), "r"(a[2]), "r"(a[3]), "r"(b[0]), "r"(b[1]));
}

// hi/lo split of 8 floats -> two packed uint4 of bf16
__device__ __forceinline__ void cvt8_split(float4 f0, float4 f1, uint4& hiw, uint4& low) {
    float v[8] = { f0.x, f0.y, f0.z, f0.w, f1.x, f1.y, f1.z, f1.w };
    unsigned short h[8], l[8];
#pragma unroll
    for (int k = 0; k < 8; ++k) {
        __nv_bfloat16 hb = __float2bfloat16(v[k]);
        __nv_bfloat16 lb = __float2bfloat16(v[k] - __bfloat162float(hb));
        h[k] = *(unsigned short*)&hb;
        l[k] = *(unsigned short*)&lb;
    }
    hiw.x = (u32)h[0] | ((u32)h[1] << 16); hiw.y = (u32)h[2] | ((u32)h[3] << 16);
    hiw.z = (u32)h[4] | ((u32)h[5] << 16); hiw.w = (u32)h[6] | ((u32)h[7] << 16);
    low.x = (u32)l[0] | ((u32)l[1] << 16); low.y = (u32)l[2] | ((u32)l[3] << 16);
    low.z = (u32)l[4] | ((u32)l[5] << 16); low.w = (u32)l[6] | ((u32)l[7] << 16);
}

// =====================================================================
// conv_split2: fp32 [rows, K] -> two bf16 planes (hi, lo), row-major.
// rz=1: first 16 blocks additionally zero g_img[0].
// =====================================================================
__global__ void conv_split2(const float* __restrict__ src,
                            unsigned short* __restrict__ dhi,
                            unsigned short* __restrict__ dlo,
                            int K, int total, int rz)
{
    if (rz && blockIdx.x < 16) {
        int i = blockIdx.x * 256 + threadIdx.x;
        if (i < 4096) ((uint4*)g_img[0])[i] = make_uint4(0u, 0u, 0u, 0u);
    }
    int t = blockIdx.x * blockDim.x + threadIdx.x;
    if (t >= total) return;
    int kg = t % (K >> 3);
    int r  = t / (K >> 3);
    const float4* p = (const float4*)(src + (size_t)r * K + kg * 8);
    float4 f0 = __ldg(p), f1 = __ldg(p + 1);
    uint4 hiw, low;
    cvt8_split(f0, f1, hiw, low);
    *(uint4*)(dhi + (size_t)r * K + kg * 8) = hiw;
    *(uint4*)(dlo + (size_t)r * K + kg * 8) = low;
}

// =====================================================================
// bf16 tensor-core GEMM, split-plane: C = (Ah+Al) @ (Wh+Wl)^T + bias
// (lo x lo term dropped). CTA 128x192, one wave (16x8 grid), k-chunk 32
// original k per iter, 4 tiles/stage (AH 8K | AL 8K | WH 12K | WL 12K),
// 3 stages = 120KB smem. Single syncthreads per iter (R15-validated).
// =====================================================================
#define GEMM_BN 192
#define GEMM_STAGE 40960
#define GEMM_SMEM (3 * GEMM_STAGE)
#define AH_OFF 0
#define AL_OFF 8192
#define WH_OFF 16384
#define WL_OFF 28672

__global__ void __launch_bounds__(256, 1) gemm_bf16_tc(
    const unsigned short* __restrict__ Ah, const unsigned short* __restrict__ Al,
    const unsigned short* __restrict__ Wh, const unsigned short* __restrict__ Wl,
    const float* __restrict__ bias, float* __restrict__ C, int K)
{
    extern __shared__ __align__(1024) char buf[];

    const int tid  = threadIdx.x;
    const int wid  = tid >> 5;
    const int lane = tid & 31;
    const int warp_m = wid & 1;
    const int warp_n = wid >> 1;
    const int m0 = blockIdx.y * 128;
    const int n0 = blockIdx.x * GEMM_BN;
    const u32 sbase = smem_u32(buf);
    const size_t strideB = (size_t)K * 2;   // bytes per row per plane
    const int niter = K / 32;

    float c[4][6][4];
#pragma unroll
    for (int i = 0; i < 4; ++i)
#pragma unroll
        for (int j = 0; j < 6; ++j)
#pragma unroll
            for (int q = 0; q < 4; ++q) c[i][j][q] = 0.f;

    const int rowL = tid >> 2;
    const int uL   = tid & 3;

#pragma unroll
    for (int s = 0; s < 2; ++s) {
        u32 ab = sbase + s * GEMM_STAGE;
#pragma unroll
        for (int q = 0; q < 2; ++q) {
            int row = rowL + q * 64;
            int p = uL ^ ((row >> 1) & 3);
            cp_async16(ab + AH_OFF + row * 64 + p * 16,
                       (const char*)Ah + (size_t)(m0 + row) * strideB + (size_t)s * 64 + uL * 16);
            cp_async16(ab + AL_OFF + row * 64 + p * 16,
                       (const char*)Al + (size_t)(m0 + row) * strideB + (size_t)s * 64 + uL * 16);
        }
#pragma unroll
        for (int q = 0; q < 3; ++q) {
            int row = rowL + q * 64;
            int p = uL ^ ((row >> 1) & 3);
            cp_async16(ab + WH_OFF + row * 64 + p * 16,
                       (const char*)Wh + (size_t)(n0 + row) * strideB + (size_t)s * 64 + uL * 16);
            cp_async16(ab + WL_OFF + row * 64 + p * 16,
                       (const char*)Wl + (size_t)(n0 + row) * strideB + (size_t)s * 64 + uL * 16);
        }
        cp_commit();
    }

    for (int i = 0; i < niter; ++i) {
        cp_wait1();
        __syncthreads();

        if (i + 2 < niter) {
            u32 ab = sbase + ((i + 2) % 3) * GEMM_STAGE;
#pragma unroll
            for (int q = 0; q < 2; ++q) {
                int row = rowL + q * 64;
                int p = uL ^ ((row >> 1) & 3);
                cp_async16(ab + AH_OFF + row * 64 + p * 16,
                           (const char*)Ah + (size_t)(m0 + row) * strideB + (size_t)(i + 2) * 64 + uL * 16);
                cp_async16(ab + AL_OFF + row * 64 + p * 16,
                           (const char*)Al + (size_t)(m0 + row) * strideB + (size_t)(i + 2) * 64 + uL * 16);
            }
#pragma unroll
            for (int q = 0; q < 3; ++q) {
                int row = rowL + q * 64;
                int p = uL ^ ((row >> 1) & 3);
                cp_async16(ab + WH_OFF + row * 64 + p * 16,
                           (const char*)Wh + (size_t)(n0 + row) * strideB + (size_t)(i + 2) * 64 + uL * 16);
                cp_async16(ab + WL_OFF + row * 64 + p * 16,
                           (const char*)Wl + (size_t)(n0 + row) * strideB + (size_t)(i + 2) * 64 + uL * 16);
            }
        }
        cp_commit();

        u32 st = sbase + (i % 3) * GEMM_STAGE;
        const int mi = lane >> 3;
        const int rl = lane & 7;
#pragma unroll
        for (int h = 0; h < 2; ++h) {
            u32 ah[4][4], al[4][4];
#pragma unroll
            for (int mt = 0; mt < 4; ++mt) {
                int row = warp_m * 64 + mt * 16 + (mi & 1) * 8 + rl;
                int u = 2 * h + (mi >> 1);
                int p = u ^ ((row >> 1) & 3);
                ldsm_x4(ah[mt], st + AH_OFF + row * 64 + p * 16);
                ldsm_x4(al[mt], st + AL_OFF + row * 64 + p * 16);
            }
            u32 bh[6][2], bl[6][2];
#pragma unroll
            for (int pp = 0; pp < 3; ++pp) {
                int j = pp * 2 + (mi >> 1);
                int row = warp_n * 48 + j * 8 + rl;
                int u = 2 * h + (mi & 1);
                int p = u ^ ((row >> 1) & 3);
                u32 r4[4];
                ldsm_x4(r4, st + WH_OFF + row * 64 + p * 16);
                bh[pp*2][0] = r4[0]; bh[pp*2][1] = r4[1];
                bh[pp*2+1][0] = r4[2]; bh[pp*2+1][1] = r4[3];
                ldsm_x4(r4, st + WL_OFF + row * 64 + p * 16);
                bl[pp*2][0] = r4[0]; bl[pp*2][1] = r4[1];
                bl[pp*2+1][0] = r4[2]; bl[pp*2+1][1] = r4[3];
            }
#pragma unroll
            for (int mt = 0; mt < 4; ++mt)
#pragma unroll
                for (int nt = 0; nt < 6; ++nt) {
                    mma16816(c[mt][nt], ah[mt], bh[nt]);
                    mma16816(c[mt][nt], al[mt], bh[nt]);
                    mma16816(c[mt][nt], ah[mt], bl[nt]);
                }
        }
    }

    const int mwb = m0 + warp_m * 64;
    const int nwb = n0 + warp_n * 48;
#pragma unroll
    for (int mt = 0; mt < 4; ++mt) {
#pragma unroll
        for (int nt = 0; nt < 6; ++nt) {
            int m = mwb + mt * 16 + (lane >> 2);
            int n = nwb + nt * 8 + (lane & 3) * 2;
            float bx = __ldg(bias + n), by = __ldg(bias + n + 1);
            float2 o0 = { c[mt][nt][0] + bx, c[mt][nt][1] + by };
            float2 o1 = { c[mt][nt][2] + bx, c[mt][nt][3] + by };
            *(float2*)(C + (size_t)m * G3 + n) = o0;
            *(float2*)(C + (size_t)(m + 8) * G3 + n) = o1;
        }
    }
}

// =====================================================================
// grid barrier — proven flat atomic/volatile protocol (gen-relative)
// =====================================================================
__device__ __forceinline__ void grid_barrier_dev() {
    __syncthreads();
    if (threadIdx.x == 0) {
        __threadfence();
        unsigned gen = g_gen;
        if (atomicAdd(&g_count, 1u) == (unsigned)(gridDim.x - 1)) {
            g_count = 0;
            __threadfence();
            g_gen = gen + 1;
        } else {
            while (g_gen == gen) { }
        }
        __threadfence();
    }
    __syncthreads();
}

// =====================================================================
// Tensor-core GRU recurrence (R14/R16 best): fragment-direct h exchange
// + register-resident weight fragments + gates prefetch.
// R17 change: layer-1 A rows written as hi/lo planes (2 stores, not 3).
// SMEM: w_hi 0..48K | w_lo 48K..96K | red 96K..108K
// =====================================================================
#define RCTA 128
#define WHI_OFF 0
#define WLO_OFF 49152
#define RED_OFF 98304
#define REC_SMEM_TC 110592

__global__ void __launch_bounds__(256, 1) gru_rec_tc(
    const float* __restrict__ w_hh, const float* __restrict__ b_hh,
    const float* __restrict__ gates,
    unsigned short* __restrict__ ahi_out, unsigned short* __restrict__ alo_out,
    float* __restrict__ hlast, int write_seq)
{
    extern __shared__ __align__(1024) char sm[];
    const u32 sb = smem_u32(sm);

    const int tid  = threadIdx.x;
    const int wid  = tid >> 5;
    const int lane = tid & 31;
    const int mi = lane >> 3;
    const int rl = lane & 7;
    const int ubase = blockIdx.x * 8;

    // ---- convert w_hh slice to split bf16 in SMEM (once) ----
    for (int idx = tid; idx < 24 * 128; idx += 256) {
        int r = idx >> 7;
        int q = idx & 127;
        int ulcl = r / 3, g = r - ulcl * 3;
        const float4* src = (const float4*)(w_hh + (size_t)(g * HH + ubase + ulcl) * HH + q * 8);
        float4 f0 = __ldg(src), f1 = __ldg(src + 1);
        uint4 hiw, low;
        cvt8_split(f0, f1, hiw, low);
        int c = q >> 2, u = q & 3;
        u32 off = (u32)(c * 1536 + r * 64 + ((u ^ ((r >> 1) & 3)) << 4));
        *(uint4*)(sm + WHI_OFF + off) = hiw;
        *(uint4*)(sm + WLO_OFF + off) = low;
    }
    __syncthreads();   // weights visible to all warps BEFORE first ldsm

    // ---- hoist B (weight) fragments into registers: 96 u32/thread ----
    u32 breg[8][12];
#pragma unroll
    for (int cc = 0; cc < 4; ++cc) {
        int ch = wid * 4 + cc;
        u32 wa = sb + WHI_OFF + ch * 1536;
        u32 wl = sb + WLO_OFF + ch * 1536;
#pragma unroll
        for (int h2 = 0; h2 < 2; ++h2) {
            int idx = cc * 2 + h2;
            int b01row = ((mi >> 1) << 3) + rl;
            int bu = 2 * h2 + (mi & 1);
            u32 b01off = (u32)(b01row * 64 + ((bu ^ ((b01row >> 1) & 3)) << 4));
            int b2row = 16 + rl;
            u32 b2off = (u32)(b2row * 64 + ((bu ^ ((b2row >> 1) & 3)) << 4));
            u32 bh01[4], bh2[4], bl01[4], bl2[4];
            ldsm_x4(bh01, wa + b01off);
            ldsm_x4(bh2,  wa + b2off);
            ldsm_x4(bl01, wl + b01off);
            ldsm_x4(bl2,  wl + b2off);
            breg[idx][0]  = bh01[0]; breg[idx][1]  = bh01[1];
            breg[idx][2]  = bh01[2]; breg[idx][3]  = bh01[3];
            breg[idx][4]  = bh2[0];  breg[idx][5]  = bh2[1];
            breg[idx][6]  = bl01[0]; breg[idx][7]  = bl01[1];
            breg[idx][8]  = bl01[2]; breg[idx][9]  = bl01[3];
            breg[idx][10] = bl2[0];  breg[idx][11] = bl2[1];
        }
    }

    // ---- epilogue constants ----
    const int ul_ep = tid >> 4;       // 0..7 local unit (tid<128)
    const int b_ep  = tid & 15;       // batch
    const int u_ep  = ubase + ul_ep;  // global unit = k index
    float bhr = 0.f, bhz = 0.f, bhn = 0.f;
    if (tid < 128) {
        bhr = b_hh[u_ep];
        bhz = b_hh[HH + u_ep];
        bhn = b_hh[2 * HH + u_ep];
    }
    const int kk_ep = u_ep & 15;
    const u32 my_off = (u32)((u_ep >> 4) * 512 +
                             ((b_ep & 7) * 4 + ((kk_ep & 7) >> 1)) * 16 +
                             (((b_ep >> 3) & 1) | ((kk_ep >> 3) << 1)) * 4 +
                             (kk_ep & 1) * 2);
    float hp = 0.f;

    const float* red = (const float*)(sm + RED_OFF);

    // ---- gates prefetch for t=0 ----
    float gxr = 0.f, gxz = 0.f, gxn = 0.f;
    if (tid < 128) {
        const float* gp = gates + (size_t)(b_ep * TT) * G3 + u_ep;
        gxr = __ldg(gp);
        gxz = __ldg(gp + HH);
        gxn = __ldg(gp + 2 * HH);
    }

    for (int t = 0; t < TT; ++t) {
        const char* img = (const char*)g_img[t & 1];

        // ---- mma phase: A from global fragment image, B from registers ----
        float cacc[3][4];
#pragma unroll
        for (int nt = 0; nt < 3; ++nt)
#pragma unroll
            for (int q = 0; q < 4; ++q) cacc[nt][q] = 0.f;

#pragma unroll
        for (int cc = 0; cc < 4; ++cc) {
#pragma unroll
            for (int h2 = 0; h2 < 2; ++h2) {
                int idx = cc * 2 + h2;
                int c16 = (wid * 4 + cc) * 2 + h2;
                const char* pa = img + c16 * 512 + lane * 16;
                u32 ahi[4], alo[4];
                ld4cg(ahi, pa);
                ld4cg(alo, pa + 32768);

                mma16816(cacc[0], ahi, &breg[idx][0]);
                mma16816(cacc[1], ahi, &breg[idx][2]);
                mma16816(cacc[2], ahi, &breg[idx][4]);
                mma16816(cacc[0], alo, &breg[idx][0]);
                mma16816(cacc[1], alo, &breg[idx][2]);
                mma16816(cacc[2], alo, &breg[idx][4]);
                mma16816(cacc[0], ahi, &breg[idx][6]);
                mma16816(cacc[1], ahi, &breg[idx][8]);
                mma16816(cacc[2], ahi, &breg[idx][10]);
            }
        }

        // ---- store partial frags, reduce across 8 warps ----
#pragma unroll
        for (int nt = 0; nt < 3; ++nt) {
            float4 v = { cacc[nt][0], cacc[nt][1], cacc[nt][2], cacc[nt][3] };
            *(float4*)(sm + RED_OFF + (size_t)(((wid * 3 + nt) * 32 + lane) << 4)) = v;
        }
        __syncthreads();

        // ---- epilogue ----
        if (tid < 128) {
            float gh[3];
#pragma unroll
            for (int g = 0; g < 3; ++g) {
                int j = ul_ep * 3 + g;
                int tile = j >> 3;
                int col = j & 7;
                int ln = (b_ep & 7) * 4 + (col >> 1);
                int rg = (col & 1) + 2 * (b_ep >> 3);
                float s = 0.f;
#pragma unroll
                for (int w8 = 0; w8 < 8; ++w8)
                    s += red[((w8 * 3 + tile) * 32 + ln) * 4 + rg];
                gh[g] = s;
            }
            float rr = 1.f / (1.f + __expf(-(gxr + gh[0] + bhr)));
            float zz = 1.f / (1.f + __expf(-(gxz + gh[1] + bhz)));
            float nn = tanhf(gxn + rr * (gh[2] + bhn));
            float hv = (1.f - zz) * nn + zz * hp;
            hp = hv;

            // write split-bf16 h into next step's image (fragment layout)
            __nv_bfloat16 hb = __float2bfloat16(hv);
            __nv_bfloat16 lb = __float2bfloat16(hv - __bfloat162float(hb));
            unsigned short hs = *(unsigned short*)&hb;
            unsigned short ls = *(unsigned short*)&lb;
            unsigned char* imgd = g_img[(t + 1) & 1];
            asm volatile("st.global.cg.b16 [%0], %1;" :: "l"(imgd + my_off), "h"(hs) : "memory");
            asm volatile("st.global.cg.b16 [%0], %1;" :: "l"(imgd + 32768 + my_off), "h"(ls) : "memory");

            if (write_seq) {
                // layer-1 GEMM A row, split planes (hi, lo)
                size_t ai = (size_t)(b_ep * TT + t) * HH + u_ep;
                asm volatile("st.global.cg.b16 [%0], %1;" :: "l"(ahi_out + ai), "h"(hs) : "memory");
                asm volatile("st.global.cg.b16 [%0], %1;" :: "l"(alo_out + ai), "h"(ls) : "memory");
            }
            if (t == TT - 1)
                hlast[b_ep * HH + u_ep] = hv;

            // prefetch next step's gates (latency hides under the barrier)
            if (t + 1 < TT) {
                const float* gp = gates + (size_t)(b_ep * TT + t + 1) * G3 + u_ep;
                gxr = __ldg(gp);
                gxz = __ldg(gp + HH);
                gxn = __ldg(gp + 2 * HH);
            }
        }

        if (t + 1 < TT) grid_barrier_dev();
    }
}

// =====================================================================
// Decoder (unchanged)
// =====================================================================
__global__ void __launch_bounds__(256) decoder_kernel(
    const float* __restrict__ h, const float* __restrict__ dw,
    const float* __restrict__ db, float* __restrict__ out)
{
    extern __shared__ __align__(16) float sh[];
    const int tid = threadIdx.x;
    for (int i = tid; i < BQ * HH / 4; i += 256)
        ((float4*)sh)[i] = ((const float4*)h)[i];
    __syncthreads();

    const int w = tid >> 5, lane = tid & 31;
#pragma unroll 1
    for (int i = 0; i < 4; ++i) {
        int n = blockIdx.x * 32 + w * 4 + i;
        float acc[16];
#pragma unroll
        for (int b = 0; b < 16; ++b) acc[b] = 0.f;
#pragma unroll
        for (int it = 0; it < 8; ++it) {
            int kq = it * 32 + lane;
            float4 wv = __ldg(((const float4*)(dw + (size_t)n * HH)) + kq);
#pragma unroll
            for (int b = 0; b < 16; ++b) {
                float4 hv = *(((const float4*)(sh + b * HH)) + kq);
                acc[b] += wv.x * hv.x + wv.y * hv.y + wv.z * hv.z + wv.w * hv.w;
            }
        }
        float myv = 0.f;
#pragma unroll
        for (int b = 0; b < 16; ++b) {
            float v = acc[b];
            v += __shfl_xor_sync(0xffffffffu, v, 16);
            v += __shfl_xor_sync(0xffffffffu, v, 8);
            v += __shfl_xor_sync(0xffffffffu, v, 4);
            v += __shfl_xor_sync(0xffffffffu, v, 2);
            v += __shfl_xor_sync(0xffffffffu, v, 1);
            if (lane == b) myv = v;
        }
        if (lane < 16) out[(size_t)lane * NNDIM + n] = myv + __ldg(db + n);
    }
}

// =====================================================================
extern "C" void kernel_launch(void* const* d_in, const int* in_sizes, int n_in,
                              void* d_out, int out_size)
{
    const float* x      = (const float*)d_in[0];
    const float* w_ih0  = (const float*)d_in[1];
    const float* w_hh0  = (const float*)d_in[2];
    const float* b_ih0  = (const float*)d_in[3];
    const float* b_hh0  = (const float*)d_in[4];
    const float* w_ih1  = (const float*)d_in[5];
    const float* w_hh1  = (const float*)d_in[6];
    const float* b_ih1  = (const float*)d_in[7];
    const float* b_hh1  = (const float*)d_in[8];
    const float* dec_w  = (const float*)d_in[9];
    const float* dec_b  = (const float*)d_in[10];
    float* out = (float*)d_out;

    float *gates, *hbuf;
    unsigned short *wcvt, *acvt;
    cudaGetSymbolAddress((void**)&gates, g_gates);
    cudaGetSymbolAddress((void**)&hbuf,  g_hbuf);
    cudaGetSymbolAddress((void**)&wcvt,  g_wcvt);
    cudaGetSymbolAddress((void**)&acvt,  g_acvt);

    cudaFuncSetAttribute(gemm_bf16_tc,
                         cudaFuncAttributeMaxDynamicSharedMemorySize, GEMM_SMEM);
    cudaFuncSetAttribute(gru_rec_tc,
                         cudaFuncAttributeMaxDynamicSharedMemorySize, REC_SMEM_TC);
    cudaFuncSetAttribute(decoder_kernel,
                         cudaFuncAttributeMaxDynamicSharedMemorySize, BQ * HH * 4);

    dim3 ggrid(G3 / GEMM_BN, (BQ * TT) / 128);   // (16, 8) = 128 CTAs, one wave

    // ---- layer 0 (K = 4096) ----
    {
        int K = NNDIM;
        size_t WK = (size_t)G3 * K, AK = (size_t)BQ * TT * K;
        int totW = G3 * (K / 8), totA = BQ * TT * (K / 8);
        conv_split2<<<(totW + 255) / 256, 256>>>(w_ih0, wcvt, wcvt + WK, K, totW, 0);
        conv_split2<<<(totA + 255) / 256, 256>>>(x,     acvt, acvt + AK, K, totA, 1);  // + zero g_img[0]
        gemm_bf16_tc<<<ggrid, 256, GEMM_SMEM>>>(acvt, acvt + AK, wcvt, wcvt + WK, b_ih0, gates, K);
    }
    {
        size_t AK1 = (size_t)BQ * TT * HH;
        gru_rec_tc<<<RCTA, 256, REC_SMEM_TC>>>(w_hh0, b_hh0, gates, acvt, acvt + AK1, hbuf, 1);
    }

    // ---- layer 1 (K = 1024; A planes written by layer-0 epilogue) ----
    {
        int K = HH;
        size_t WK = (size_t)G3 * K, AK = (size_t)BQ * TT * K;
        int totW = G3 * (K / 8);
        conv_split2<<<(totW + 255) / 256, 256>>>(w_ih1, wcvt, wcvt + WK, K, totW, 1);  // + zero g_img[0]
        gemm_bf16_tc<<<ggrid, 256, GEMM_SMEM>>>(acvt, acvt + AK, wcvt, wcvt + WK, b_ih1, gates, K);
    }
    {
        size_t AK1 = (size_t)BQ * TT * HH;
        gru_rec_tc<<<RCTA, 256, REC_SMEM_TC>>>(w_hh1, b_hh1, gates, acvt, acvt + AK1, hbuf, 0);
    }

    // ---- decoder ----
    decoder_kernel<<<NNDIM / 32, 256, BQ * HH * 4>>>(hbuf, dec_w, dec_b, out);
}